// round 14
// baseline (speedup 1.0000x reference)
#include <cuda_runtime.h>
#include <cuda_bf16.h>
#include <cstdint>
#include <cmath>

#define NROWS 8192
#define BHALF 4096
#define DDIM  512
#define INV_T 14.285714285714286f
// log2(e)/T
#define EXP_SCALE 20.60992915555662f
#define SPANS 128              // one partial per 64-col span (collision-free)
#define SROW 40                // padded smem row (bf16 units): 80B, conflict-free
#define NTILES 2080            // 64*65/2 upper-triangle tiles
#define NORMBLOCKS 1024        // 4 pairs per block
#define STAGE_B (128 * SROW * 2 * 2)   // bytes per stage (sA + sB) = 20480
#define SMEM_BYTES (3 * STAGE_B)       // 61440  (3-stage: proven optimum)
#define RBLOCKS 1024

// ---------------- device scratch (no allocation allowed) ----------------
__device__ __nv_bfloat16 g_fb16[(size_t)NROWS * DDIM];      // 8 MB normalized bf16
__device__ float         g_partial[(size_t)NROWS * SPANS];  // 4 MB [row][span]
__device__ float         g_pos [NROWS];
__device__ float         g_blocksum[RBLOCKS];
__device__ unsigned      g_cnt;                             // zero-init, self-resetting
__device__ unsigned      g_grp[32];                         // per-group ready counters

// ---------------- PTX helpers (plain sm_103-legal only) ----------------
__device__ __forceinline__ uint32_t smem_u32(const void* p) {
    uint32_t a;
    asm("{ .reg .u64 t; cvta.to.shared.u64 t, %1; cvt.u32.u64 %0, t; }" : "=r"(a) : "l"(p));
    return a;
}

__device__ __forceinline__ void cp16(uint32_t s, const void* g) {
    asm volatile("cp.async.cg.shared.global [%0], [%1], 16;" :: "r"(s), "l"(g) : "memory");
}
__device__ __forceinline__ void cp_commit() {
    asm volatile("cp.async.commit_group;" ::: "memory");
}
template<int N> __device__ __forceinline__ void cp_wait() {
    asm volatile("cp.async.wait_group %0;" :: "n"(N) : "memory");
}

__device__ __forceinline__ void ldsm_x4(uint32_t* r, uint32_t addr) {
    asm volatile("ldmatrix.sync.aligned.m8n8.x4.shared.b16 {%0,%1,%2,%3}, [%4];"
                 : "=r"(r[0]), "=r"(r[1]), "=r"(r[2]), "=r"(r[3]) : "r"(addr));
}

__device__ __forceinline__ void mma16816(float* c, const uint32_t* a, uint32_t b0, uint32_t b1) {
    asm volatile(
        "mma.sync.aligned.m16n8k16.row.col.f32.bf16.bf16.f32 "
        "{%0,%1,%2,%3}, {%4,%5,%6,%7}, {%8,%9}, {%0,%1,%2,%3};"
        : "+f"(c[0]), "+f"(c[1]), "+f"(c[2]), "+f"(c[3])
        : "r"(a[0]), "r"(a[1]), "r"(a[2]), "r"(a[3]), "r"(b0), "r"(b1));
}

__device__ __forceinline__ float ex2f(float x) {
    float y;
    asm("ex2.approx.ftz.f32 %0, %1;" : "=f"(y) : "f"(x));
    return y;
}

// ---------------- fused kernel: norm blocks (0..1023) then sim tiles -----------
// Sim tiles enumerated CT-MAJOR (u = ct(ct+1)/2 + rt) so the earliest sim CTAs
// depend only on the earliest norm groups -> real norm/sim overlap.
__global__ void __launch_bounds__(128) fused_kernel(
        const float* __restrict__ logits, const float* __restrict__ label) {
    extern __shared__ char smem[];
    int tid = threadIdx.x;
    int w = tid >> 5, lane = tid & 31;

    if (blockIdx.x < NORMBLOCKS) {
        // ---------------- norm role ----------------
        int i = blockIdx.x * 4 + w;
        const float4* ap = (const float4*)(logits + (size_t)i * DDIM);
        const float4* bp = (const float4*)(label  + (size_t)i * DDIM);

        float4 av[4], bv[4];
        float ssa = 0.f, ssb = 0.f, ab = 0.f;
        #pragma unroll
        for (int j = 0; j < 4; j++) {
            av[j] = ap[lane + 32 * j];
            bv[j] = bp[lane + 32 * j];
            ssa += av[j].x * av[j].x + av[j].y * av[j].y + av[j].z * av[j].z + av[j].w * av[j].w;
            ssb += bv[j].x * bv[j].x + bv[j].y * bv[j].y + bv[j].z * bv[j].z + bv[j].w * bv[j].w;
            ab  += av[j].x * bv[j].x + av[j].y * bv[j].y + av[j].z * bv[j].z + av[j].w * bv[j].w;
        }
        #pragma unroll
        for (int o = 16; o; o >>= 1) {
            ssa += __shfl_xor_sync(0xffffffffu, ssa, o);
            ssb += __shfl_xor_sync(0xffffffffu, ssb, o);
            ab  += __shfl_xor_sync(0xffffffffu, ab, o);
        }
        float sa = 1.0f / fmaxf(sqrtf(ssa), 1e-12f);
        float sb = 1.0f / fmaxf(sqrtf(ssb), 1e-12f);

        uint2* oa = (uint2*)(g_fb16 + (size_t)i * DDIM);
        uint2* ob = (uint2*)(g_fb16 + (size_t)(i + BHALF) * DDIM);
        #pragma unroll
        for (int j = 0; j < 4; j++) {
            __nv_bfloat162 h0, h1;
            uint2 pk;
            h0.x = __float2bfloat16(av[j].x * sa); h0.y = __float2bfloat16(av[j].y * sa);
            h1.x = __float2bfloat16(av[j].z * sa); h1.y = __float2bfloat16(av[j].w * sa);
            pk.x = *reinterpret_cast<uint32_t*>(&h0);
            pk.y = *reinterpret_cast<uint32_t*>(&h1);
            oa[lane + 32 * j] = pk;
            h0.x = __float2bfloat16(bv[j].x * sb); h0.y = __float2bfloat16(bv[j].y * sb);
            h1.x = __float2bfloat16(bv[j].z * sb); h1.y = __float2bfloat16(bv[j].w * sb);
            pk.x = *reinterpret_cast<uint32_t*>(&h0);
            pk.y = *reinterpret_cast<uint32_t*>(&h1);
            ob[lane + 32 * j] = pk;
        }
        if (lane == 0) {
            float p = ab * sa * sb * INV_T;
            g_pos[i] = p;
            g_pos[i + BHALF] = p;
        }
        // release: all stores done -> bump this block's group counter
        __syncthreads();
        if (tid == 0) {
            __threadfence();
            atomicAdd(&g_grp[blockIdx.x >> 5], 1u);
        }
        return;
    }

    // ---------------- sim role (EXACT R10 inner code, ct-major decode) --------
    int g = lane >> 2, t = lane & 3;
    int warp_m = w & 1, warp_n = w >> 1;

    // decode ct-major: u = ct*(ct+1)/2 + rt, rt <= ct
    int u = blockIdx.x - NORMBLOCKS;
    int ct = (int)((sqrt(8.0 * (double)u + 1.0) - 1.0) * 0.5);
    while ((ct + 1) * (ct + 2) / 2 <= u) ct++;
    while (ct * (ct + 1) / 2 > u) ct--;
    int rt = u - ct * (ct + 1) / 2;
    bool diag = (rt == ct);

    // acquire: wait for both needed 128-row groups to be normalized
    if (tid == 0) {
        volatile unsigned* vg = (volatile unsigned*)g_grp;
        while (vg[rt & 31] < 32u) __nanosleep(64);
        while (vg[ct & 31] < 32u) __nanosleep(64);
        __threadfence();
    }
    __syncthreads();

    const __nv_bfloat16* Ag = g_fb16 + (size_t)rt * 128 * DDIM;
    const __nv_bfloat16* Bg = g_fb16 + (size_t)ct * 128 * DDIM;

    float acc[4][8][4];
    #pragma unroll
    for (int mf = 0; mf < 4; mf++)
        #pragma unroll
        for (int nf = 0; nf < 8; nf++)
            #pragma unroll
            for (int j = 0; j < 4; j++) acc[mf][nf][j] = 0.f;

    uint32_t sbase = smem_u32(smem);

    // issue one 32-wide K chunk into stage `s` (8 cp16 per thread)
    auto issue = [&](int s, int kc) {
        uint32_t aB = sbase + (uint32_t)s * STAGE_B;
        uint32_t bB = aB + 128 * SROW * 2;
        #pragma unroll
        for (int i = 0; i < 4; i++) {
            int idx = tid + 128 * i;        // 0..511
            int row = idx >> 2, seg = idx & 3;
            size_t goff = (size_t)row * DDIM + kc * 32 + seg * 8;
            uint32_t soff = (uint32_t)(row * SROW + seg * 8) * 2;
            cp16(aB + soff, Ag + goff);
            cp16(bB + soff, Bg + goff);
        }
        cp_commit();
    };

    issue(0, 0);
    issue(1, 1);

    for (int kc = 0; kc < 16; kc++) {
        cp_wait<1>();          // stage kc landed
        __syncthreads();       // everyone done reading stage being overwritten
        if (kc + 2 < 16) issue((kc + 2) % 3, kc + 2);
        else cp_commit();      // empty group keeps wait_group accounting exact

        uint32_t aBase = sbase + (uint32_t)(kc % 3) * STAGE_B;
        uint32_t bBase = aBase + 128 * SROW * 2;

        #pragma unroll
        for (int ks = 0; ks < 2; ks++) {
            // A frags: 4 x ldmatrix.x4 (mf = 0..3)
            uint32_t afr[4][4];
            {
                int mrow = lane & 7;
                int msel = lane >> 3;                 // 0..3
                int rofs = (msel & 1) * 8 + mrow;
                int cofs = ks * 16 + (msel >> 1) * 8;
                #pragma unroll
                for (int mf = 0; mf < 4; mf++) {
                    int row = warp_m * 64 + mf * 16 + rofs;
                    ldsm_x4(afr[mf], aBase + (uint32_t)(row * SROW + cofs) * 2);
                }
            }
            // B frags: 4 x ldmatrix.x4, each covers 2 nf
            uint32_t bfr[8][2];
            {
                int mrow = lane & 7;
                int msel = lane >> 3;
                int rofs = (msel >> 1) * 8 + mrow;    // second matrix pair = nf+1
                int cofs = ks * 16 + (msel & 1) * 8;
                #pragma unroll
                for (int np = 0; np < 4; np++) {
                    uint32_t r4[4];
                    int row = warp_n * 64 + np * 16 + rofs;
                    ldsm_x4(r4, bBase + (uint32_t)(row * SROW + cofs) * 2);
                    bfr[np * 2][0]     = r4[0];
                    bfr[np * 2][1]     = r4[1];
                    bfr[np * 2 + 1][0] = r4[2];
                    bfr[np * 2 + 1][1] = r4[3];
                }
            }
            #pragma unroll
            for (int mf = 0; mf < 4; mf++)
                #pragma unroll
                for (int nf = 0; nf < 8; nf++)
                    mma16816(acc[mf][nf], afr[mf], bfr[nf][0], bfr[nf][1]);
        }
    }

    // -------- epilogue: exp, diag mask, row sums + (off-diag) col sums --------
    int rbase = rt * 128 + warp_m * 64;
    int cbase = ct * 128 + warp_n * 64;
    float rs[4][2];
    #pragma unroll
    for (int mf = 0; mf < 4; mf++) { rs[mf][0] = 0.f; rs[mf][1] = 0.f; }

    #pragma unroll
    for (int nf = 0; nf < 8; nf++) {
        float cs0 = 0.f, cs1 = 0.f;
        int c0 = cbase + nf * 8 + 2 * t;
        #pragma unroll
        for (int mf = 0; mf < 4; mf++) {
            const float* c = acc[mf][nf];
            float e0 = ex2f(c[0] * EXP_SCALE);
            float e1 = ex2f(c[1] * EXP_SCALE);
            float e2 = ex2f(c[2] * EXP_SCALE);
            float e3 = ex2f(c[3] * EXP_SCALE);
            if (diag) {
                int r0 = rbase + mf * 16 + g;
                if (c0     == r0)     e0 = 0.f;
                if (c0 + 1 == r0)     e1 = 0.f;
                if (c0     == r0 + 8) e2 = 0.f;
                if (c0 + 1 == r0 + 8) e3 = 0.f;
            }
            rs[mf][0] += e0 + e1;
            rs[mf][1] += e2 + e3;
            cs0 += e0 + e2;
            cs1 += e1 + e3;
        }
        if (!diag) {
            // reduce over g (lanes differing in bits 2..4)
            #pragma unroll
            for (int o = 4; o <= 16; o <<= 1) {
                cs0 += __shfl_xor_sync(0xffffffffu, cs0, o);
                cs1 += __shfl_xor_sync(0xffffffffu, cs1, o);
            }
            if (g == 0) {
                int span = rt * 2 + warp_m;   // transposed contribution
                g_partial[(size_t)c0 * SPANS + span]       = cs0;
                g_partial[(size_t)(c0 + 1) * SPANS + span] = cs1;
            }
        }
    }
    #pragma unroll
    for (int mf = 0; mf < 4; mf++) {
        float s0 = rs[mf][0], s1 = rs[mf][1];
        s0 += __shfl_xor_sync(0xffffffffu, s0, 1);
        s0 += __shfl_xor_sync(0xffffffffu, s0, 2);
        s1 += __shfl_xor_sync(0xffffffffu, s1, 1);
        s1 += __shfl_xor_sync(0xffffffffu, s1, 2);
        if (t == 0) {
            int r0 = rbase + mf * 16 + g;
            int span = ct * 2 + warp_n;       // row sums
            g_partial[(size_t)r0 * SPANS + span]       = s0;
            g_partial[(size_t)(r0 + 8) * SPANS + span] = s1;
        }
    }
}

// ---- reduce: per-row lse - pos + grid-wide mean (last-block pattern) ----------
// Also resets g_grp for the next graph replay (runs strictly after all sim work).
__global__ void __launch_bounds__(256) reduce_kernel(float* __restrict__ out) {
    int tid = threadIdx.x;
    int warp = tid >> 5, lane = tid & 31;
    if (blockIdx.x == 0 && tid < 32) g_grp[tid] = 0;   // replay reset
    int row = blockIdx.x * 8 + warp;
    float4 v = ((const float4*)(g_partial + (size_t)row * SPANS))[lane];
    float s = (v.x + v.y) + (v.z + v.w);
    #pragma unroll
    for (int o = 16; o; o >>= 1) s += __shfl_xor_sync(0xffffffffu, s, o);

    __shared__ float ws[8];
    __shared__ int lastFlag;
    if (lane == 0) ws[warp] = logf(s) - g_pos[row];
    __syncthreads();
    if (tid == 0) {
        float bs = 0.f;
        #pragma unroll
        for (int i = 0; i < 8; i++) bs += ws[i];
        g_blocksum[blockIdx.x] = bs;
        __threadfence();
        unsigned old = atomicAdd(&g_cnt, 1u);
        lastFlag = (old == RBLOCKS - 1);
    }
    __syncthreads();
    if (lastFlag) {
        float a = 0.f;
        #pragma unroll
        for (int i = 0; i < RBLOCKS / 256; i++) a += g_blocksum[tid + 256 * i];
        #pragma unroll
        for (int o = 16; o; o >>= 1) a += __shfl_xor_sync(0xffffffffu, a, o);
        __shared__ float fs[8];
        if (lane == 0) fs[warp] = a;
        __syncthreads();
        if (tid == 0) {
            float tot = 0.f;
            #pragma unroll
            for (int i = 0; i < 8; i++) tot += fs[i];
            out[0] = tot * (1.0f / (float)NROWS);
            g_cnt = 0;     // reset for next graph replay
        }
    }
}

// ---------------- launch ----------------
extern "C" void kernel_launch(void* const* d_in, const int* in_sizes, int n_in,
                              void* d_out, int out_size) {
    const float* logits = (const float*)d_in[0];
    const float* label  = (const float*)d_in[1];
    float* out = (float*)d_out;

    cudaFuncSetAttribute(fused_kernel, cudaFuncAttributeMaxDynamicSharedMemorySize,
                         SMEM_BYTES);

    fused_kernel<<<NORMBLOCKS + NTILES, 128, SMEM_BYTES>>>(logits, label);
    reduce_kernel<<<RBLOCKS, 256>>>(out);
}

// round 15
// speedup vs baseline: 1.0349x; 1.0349x over previous
#include <cuda_runtime.h>
#include <cuda_bf16.h>
#include <cstdint>
#include <cmath>

#define NROWS 8192
#define BHALF 4096
#define DDIM  512
#define INV_T 14.285714285714286f
// log2(e)/T
#define EXP_SCALE 20.60992915555662f
#define SPANS 128              // one partial per 64-col span (collision-free)
#define SROW 40                // padded smem row (bf16 units): 80B, conflict-free
#define NTILES 2080            // 64*65/2 upper-triangle tiles
#define STAGE_B (128 * SROW * 2 * 2)   // bytes per stage (sA + sB) = 20480
#define SMEM_BYTES (3 * STAGE_B)       // 61440  (3-stage: proven optimum)
#define RBLOCKS 1024

// ---------------- device scratch (no allocation allowed) ----------------
__device__ __nv_bfloat16 g_fb16[(size_t)NROWS * DDIM];      // 8 MB normalized bf16
__device__ float         g_partial[(size_t)NROWS * SPANS];  // 4 MB [row][span]
__device__ float         g_pos [NROWS];
__device__ float         g_blocksum[RBLOCKS];
__device__ unsigned      g_cnt;                             // zero-init, self-resetting

// ---------------- PTX helpers (plain sm_103-legal only) ----------------
__device__ __forceinline__ uint32_t smem_u32(const void* p) {
    uint32_t a;
    asm("{ .reg .u64 t; cvta.to.shared.u64 t, %1; cvt.u32.u64 %0, t; }" : "=r"(a) : "l"(p));
    return a;
}

__device__ __forceinline__ void cp16(uint32_t s, const void* g) {
    asm volatile("cp.async.cg.shared.global [%0], [%1], 16;" :: "r"(s), "l"(g) : "memory");
}
__device__ __forceinline__ void cp_commit() {
    asm volatile("cp.async.commit_group;" ::: "memory");
}
template<int N> __device__ __forceinline__ void cp_wait() {
    asm volatile("cp.async.wait_group %0;" :: "n"(N) : "memory");
}

__device__ __forceinline__ void ldsm_x4(uint32_t* r, uint32_t addr) {
    asm volatile("ldmatrix.sync.aligned.m8n8.x4.shared.b16 {%0,%1,%2,%3}, [%4];"
                 : "=r"(r[0]), "=r"(r[1]), "=r"(r[2]), "=r"(r[3]) : "r"(addr));
}

__device__ __forceinline__ void mma16816(float* c, const uint32_t* a, uint32_t b0, uint32_t b1) {
    asm volatile(
        "mma.sync.aligned.m16n8k16.row.col.f32.bf16.bf16.f32 "
        "{%0,%1,%2,%3}, {%4,%5,%6,%7}, {%8,%9}, {%0,%1,%2,%3};"
        : "+f"(c[0]), "+f"(c[1]), "+f"(c[2]), "+f"(c[3])
        : "r"(a[0]), "r"(a[1]), "r"(a[2]), "r"(a[3]), "r"(b0), "r"(b1));
}

__device__ __forceinline__ float ex2f(float x) {
    float y;
    asm("ex2.approx.ftz.f32 %0, %1;" : "=f"(y) : "f"(x));
    return y;
}

// ---- kernel 1: fused normalize + positives, warp-per-pair (R10 proven best) ---
__global__ void __launch_bounds__(256) norm_pos_kernel(
        const float* __restrict__ logits, const float* __restrict__ label) {
    int i = blockIdx.x * 8 + (threadIdx.x >> 5);
    int lane = threadIdx.x & 31;
    const float4* ap = (const float4*)(logits + (size_t)i * DDIM);
    const float4* bp = (const float4*)(label  + (size_t)i * DDIM);

    float4 av[4], bv[4];
    float ssa = 0.f, ssb = 0.f, ab = 0.f;
    #pragma unroll
    for (int j = 0; j < 4; j++) {
        av[j] = ap[lane + 32 * j];
        bv[j] = bp[lane + 32 * j];
        ssa += av[j].x * av[j].x + av[j].y * av[j].y + av[j].z * av[j].z + av[j].w * av[j].w;
        ssb += bv[j].x * bv[j].x + bv[j].y * bv[j].y + bv[j].z * bv[j].z + bv[j].w * bv[j].w;
        ab  += av[j].x * bv[j].x + av[j].y * bv[j].y + av[j].z * bv[j].z + av[j].w * bv[j].w;
    }
    #pragma unroll
    for (int o = 16; o; o >>= 1) {
        ssa += __shfl_xor_sync(0xffffffffu, ssa, o);
        ssb += __shfl_xor_sync(0xffffffffu, ssb, o);
        ab  += __shfl_xor_sync(0xffffffffu, ab, o);
    }
    float sa = 1.0f / fmaxf(sqrtf(ssa), 1e-12f);
    float sb = 1.0f / fmaxf(sqrtf(ssb), 1e-12f);

    uint2* oa = (uint2*)(g_fb16 + (size_t)i * DDIM);
    uint2* ob = (uint2*)(g_fb16 + (size_t)(i + BHALF) * DDIM);
    #pragma unroll
    for (int j = 0; j < 4; j++) {
        __nv_bfloat162 h0, h1;
        uint2 pk;
        h0.x = __float2bfloat16(av[j].x * sa); h0.y = __float2bfloat16(av[j].y * sa);
        h1.x = __float2bfloat16(av[j].z * sa); h1.y = __float2bfloat16(av[j].w * sa);
        pk.x = *reinterpret_cast<uint32_t*>(&h0);
        pk.y = *reinterpret_cast<uint32_t*>(&h1);
        oa[lane + 32 * j] = pk;
        h0.x = __float2bfloat16(bv[j].x * sb); h0.y = __float2bfloat16(bv[j].y * sb);
        h1.x = __float2bfloat16(bv[j].z * sb); h1.y = __float2bfloat16(bv[j].w * sb);
        pk.x = *reinterpret_cast<uint32_t*>(&h0);
        pk.y = *reinterpret_cast<uint32_t*>(&h1);
        ob[lane + 32 * j] = pk;
    }
    if (lane == 0) {
        float p = ab * sa * sb * INV_T;
        g_pos[i] = p;
        g_pos[i + BHALF] = p;
    }
}

// ---------------- kernel 2: symmetric 128x128 sim tiles (upper triangle) -------
// EXACT R10 configuration (proven 117.9us): 4 warps, warp tile 64x64, bf16
// m16n8k16, kc=32, 3-stage cp.async, wait<1>, one __syncthreads per chunk.
__global__ void __launch_bounds__(128) sim_kernel() {
    extern __shared__ char smem[];

    int tid = threadIdx.x;
    int w = tid >> 5, lane = tid & 31;
    int g = lane >> 2, t = lane & 3;
    int warp_m = w & 1, warp_n = w >> 1;

    // decode upper-triangle tile (rt, ct), ct >= rt
    int u = blockIdx.x;
    int rt = (int)((129.0 - sqrt(129.0 * 129.0 - 8.0 * (double)u)) * 0.5);
    while (64 * (rt + 1) - ((rt + 1) * rt) / 2 <= u) rt++;
    while (64 * rt - (rt * (rt - 1)) / 2 > u) rt--;
    int ct = rt + (u - (64 * rt - (rt * (rt - 1)) / 2));
    bool diag = (rt == ct);

    const __nv_bfloat16* Ag = g_fb16 + (size_t)rt * 128 * DDIM;
    const __nv_bfloat16* Bg = g_fb16 + (size_t)ct * 128 * DDIM;

    float acc[4][8][4];
    #pragma unroll
    for (int mf = 0; mf < 4; mf++)
        #pragma unroll
        for (int nf = 0; nf < 8; nf++)
            #pragma unroll
            for (int j = 0; j < 4; j++) acc[mf][nf][j] = 0.f;

    uint32_t sbase = smem_u32(smem);

    // issue one 32-wide K chunk into stage `s` (8 cp16 per thread)
    auto issue = [&](int s, int kc) {
        uint32_t aB = sbase + (uint32_t)s * STAGE_B;
        uint32_t bB = aB + 128 * SROW * 2;
        #pragma unroll
        for (int i = 0; i < 4; i++) {
            int idx = tid + 128 * i;        // 0..511
            int row = idx >> 2, seg = idx & 3;
            size_t goff = (size_t)row * DDIM + kc * 32 + seg * 8;
            uint32_t soff = (uint32_t)(row * SROW + seg * 8) * 2;
            cp16(aB + soff, Ag + goff);
            cp16(bB + soff, Bg + goff);
        }
        cp_commit();
    };

    issue(0, 0);
    issue(1, 1);

    for (int kc = 0; kc < 16; kc++) {
        cp_wait<1>();          // stage kc landed
        __syncthreads();       // everyone done reading stage being overwritten
        if (kc + 2 < 16) issue((kc + 2) % 3, kc + 2);
        else cp_commit();      // empty group keeps wait_group accounting exact

        uint32_t aBase = sbase + (uint32_t)(kc % 3) * STAGE_B;
        uint32_t bBase = aBase + 128 * SROW * 2;

        #pragma unroll
        for (int ks = 0; ks < 2; ks++) {
            // A frags: 4 x ldmatrix.x4 (mf = 0..3)
            uint32_t afr[4][4];
            {
                int mrow = lane & 7;
                int msel = lane >> 3;                 // 0..3
                int rofs = (msel & 1) * 8 + mrow;
                int cofs = ks * 16 + (msel >> 1) * 8;
                #pragma unroll
                for (int mf = 0; mf < 4; mf++) {
                    int row = warp_m * 64 + mf * 16 + rofs;
                    ldsm_x4(afr[mf], aBase + (uint32_t)(row * SROW + cofs) * 2);
                }
            }
            // B frags: 4 x ldmatrix.x4, each covers 2 nf
            uint32_t bfr[8][2];
            {
                int mrow = lane & 7;
                int msel = lane >> 3;
                int rofs = (msel >> 1) * 8 + mrow;    // second matrix pair = nf+1
                int cofs = ks * 16 + (msel & 1) * 8;
                #pragma unroll
                for (int np = 0; np < 4; np++) {
                    uint32_t r4[4];
                    int row = warp_n * 64 + np * 16 + rofs;
                    ldsm_x4(r4, bBase + (uint32_t)(row * SROW + cofs) * 2);
                    bfr[np * 2][0]     = r4[0];
                    bfr[np * 2][1]     = r4[1];
                    bfr[np * 2 + 1][0] = r4[2];
                    bfr[np * 2 + 1][1] = r4[3];
                }
            }
            #pragma unroll
            for (int mf = 0; mf < 4; mf++)
                #pragma unroll
                for (int nf = 0; nf < 8; nf++)
                    mma16816(acc[mf][nf], afr[mf], bfr[nf][0], bfr[nf][1]);
        }
    }

    // -------- epilogue: exp, diag mask, row sums + (off-diag) col sums --------
    int rbase = rt * 128 + warp_m * 64;
    int cbase = ct * 128 + warp_n * 64;
    float rs[4][2];
    #pragma unroll
    for (int mf = 0; mf < 4; mf++) { rs[mf][0] = 0.f; rs[mf][1] = 0.f; }

    #pragma unroll
    for (int nf = 0; nf < 8; nf++) {
        float cs0 = 0.f, cs1 = 0.f;
        int c0 = cbase + nf * 8 + 2 * t;
        #pragma unroll
        for (int mf = 0; mf < 4; mf++) {
            const float* c = acc[mf][nf];
            float e0 = ex2f(c[0] * EXP_SCALE);
            float e1 = ex2f(c[1] * EXP_SCALE);
            float e2 = ex2f(c[2] * EXP_SCALE);
            float e3 = ex2f(c[3] * EXP_SCALE);
            if (diag) {
                int r0 = rbase + mf * 16 + g;
                if (c0     == r0)     e0 = 0.f;
                if (c0 + 1 == r0)     e1 = 0.f;
                if (c0     == r0 + 8) e2 = 0.f;
                if (c0 + 1 == r0 + 8) e3 = 0.f;
            }
            rs[mf][0] += e0 + e1;
            rs[mf][1] += e2 + e3;
            cs0 += e0 + e2;
            cs1 += e1 + e3;
        }
        if (!diag) {
            // reduce over g (lanes differing in bits 2..4)
            #pragma unroll
            for (int o = 4; o <= 16; o <<= 1) {
                cs0 += __shfl_xor_sync(0xffffffffu, cs0, o);
                cs1 += __shfl_xor_sync(0xffffffffu, cs1, o);
            }
            if (g == 0) {
                int span = rt * 2 + warp_m;   // transposed contribution
                g_partial[(size_t)c0 * SPANS + span]       = cs0;
                g_partial[(size_t)(c0 + 1) * SPANS + span] = cs1;
            }
        }
    }
    #pragma unroll
    for (int mf = 0; mf < 4; mf++) {
        float s0 = rs[mf][0], s1 = rs[mf][1];
        s0 += __shfl_xor_sync(0xffffffffu, s0, 1);
        s0 += __shfl_xor_sync(0xffffffffu, s0, 2);
        s1 += __shfl_xor_sync(0xffffffffu, s1, 1);
        s1 += __shfl_xor_sync(0xffffffffu, s1, 2);
        if (t == 0) {
            int r0 = rbase + mf * 16 + g;
            int span = ct * 2 + warp_n;       // row sums
            g_partial[(size_t)r0 * SPANS + span]       = s0;
            g_partial[(size_t)(r0 + 8) * SPANS + span] = s1;
        }
    }
}

// ---- kernel 3: fused per-row lse - pos + grid-wide mean (last-block pattern) --
__global__ void __launch_bounds__(256) reduce_kernel(float* __restrict__ out) {
    int tid = threadIdx.x;
    int warp = tid >> 5, lane = tid & 31;
    int row = blockIdx.x * 8 + warp;
    float4 v = ((const float4*)(g_partial + (size_t)row * SPANS))[lane];
    float s = (v.x + v.y) + (v.z + v.w);
    #pragma unroll
    for (int o = 16; o; o >>= 1) s += __shfl_xor_sync(0xffffffffu, s, o);

    __shared__ float ws[8];
    __shared__ int lastFlag;
    if (lane == 0) ws[warp] = logf(s) - g_pos[row];
    __syncthreads();
    if (tid == 0) {
        float bs = 0.f;
        #pragma unroll
        for (int i = 0; i < 8; i++) bs += ws[i];
        g_blocksum[blockIdx.x] = bs;
        __threadfence();
        unsigned old = atomicAdd(&g_cnt, 1u);
        lastFlag = (old == RBLOCKS - 1);
    }
    __syncthreads();
    if (lastFlag) {
        float a = 0.f;
        #pragma unroll
        for (int i = 0; i < RBLOCKS / 256; i++) a += g_blocksum[tid + 256 * i];
        #pragma unroll
        for (int o = 16; o; o >>= 1) a += __shfl_xor_sync(0xffffffffu, a, o);
        __shared__ float fs[8];
        if (lane == 0) fs[warp] = a;
        __syncthreads();
        if (tid == 0) {
            float tot = 0.f;
            #pragma unroll
            for (int i = 0; i < 8; i++) tot += fs[i];
            out[0] = tot * (1.0f / (float)NROWS);
            g_cnt = 0;     // reset for next graph replay
        }
    }
}

// ---------------- launch ----------------
extern "C" void kernel_launch(void* const* d_in, const int* in_sizes, int n_in,
                              void* d_out, int out_size) {
    const float* logits = (const float*)d_in[0];
    const float* label  = (const float*)d_in[1];
    float* out = (float*)d_out;

    cudaFuncSetAttribute(sim_kernel, cudaFuncAttributeMaxDynamicSharedMemorySize,
                         SMEM_BYTES);

    norm_pos_kernel<<<BHALF / 8, 256>>>(logits, label);
    sim_kernel<<<NTILES, 128, SMEM_BYTES>>>();
    reduce_kernel<<<RBLOCKS, 256>>>(out);
}